// round 11
// baseline (speedup 1.0000x reference)
#include <cuda_runtime.h>
#include <cuda_bf16.h>
#include <cstdint>

#define TOKENS 16384
#define IN_F   4096
#define OUT_F  4096

#define BM 128
#define BN 128
#define BKE 64                        // K elements per chunk
#define ROWB 128                      // bytes per smem row (64 bf16)
#define STAGES 3
#define NCHUNK (IN_F / BKE)           // 64
#define A_BYTES (BM * ROWB)           // 16 KB
#define STAGE_BYTES (2 * BM * ROWB)   // 32 KB
#define OFF_SCALE (STAGES * STAGE_BYTES)   // 98304: scale/bias staging
#define SMEM_DYN (OFF_SCALE + 1536)

#define GT 128                        // GEMM threads: 4 warps, 64x64 warp tiles

#define UNPACK_BLOCKS ((OUT_F * (IN_F / 2) / 4) / 256)   // 8192

// ---------------- device scratch ----------------
__device__ __nv_bfloat16 g_act[(size_t)TOKENS * IN_F];   // 128 MB bf16 integer activations
__device__ float         g_act_scale[TOKENS];
__device__ __nv_bfloat16 g_wb[(size_t)OUT_F * IN_F];     // 32 MB bf16 integer weights (K-major)

// ---------------- helpers ----------------
__device__ __forceinline__ uint32_t smem_u32(const void* p) {
    uint32_t a;
    asm("{ .reg .u64 t; cvta.to.shared.u64 t, %1; cvt.u32.u64 %0, t; }" : "=r"(a) : "l"(p));
    return a;
}
// 16B-chunk xor swizzle within a 128B row: conflict-free for 8-row ldmatrix phases
__device__ __forceinline__ uint32_t swz(uint32_t row, uint32_t kc) {
    return row * ROWB + ((kc ^ (row & 7u)) << 4);
}
__device__ __forceinline__ void cp16(uint32_t d, const void* g) {
    asm volatile("cp.async.cg.shared.global [%0], [%1], 16;" :: "r"(d), "l"(g) : "memory");
}
__device__ __forceinline__ void cp4(uint32_t d, const void* g) {
    asm volatile("cp.async.ca.shared.global [%0], [%1], 4;" :: "r"(d), "l"(g) : "memory");
}
__device__ __forceinline__ void ldm_x4(uint32_t* r, uint32_t addr) {
    asm volatile("ldmatrix.sync.aligned.m8n8.x4.shared.b16 {%0,%1,%2,%3}, [%4];"
                 : "=r"(r[0]), "=r"(r[1]), "=r"(r[2]), "=r"(r[3]) : "r"(addr));
}
__device__ __forceinline__ void mma_bf16(float* c, const uint32_t* a, uint32_t b0, uint32_t b1) {
    asm volatile("mma.sync.aligned.m16n8k16.row.col.f32.bf16.bf16.f32 "
                 "{%0,%1,%2,%3}, {%4,%5,%6,%7}, {%8,%9}, {%0,%1,%2,%3};"
                 : "+f"(c[0]), "+f"(c[1]), "+f"(c[2]), "+f"(c[3])
                 : "r"(a[0]), "r"(a[1]), "r"(a[2]), "r"(a[3]), "r"(b0), "r"(b1));
}

// ---------------- kernel 1: fused prep (quant rows + weight unpack) ----------------
__global__ void __launch_bounds__(256) prep_kernel(const float* __restrict__ x,
                                                   const int* __restrict__ qw)
{
    if (blockIdx.x >= TOKENS) {
        size_t idx = (size_t)(blockIdx.x - TOKENS) * 256 + threadIdx.x;
        int4 qv = reinterpret_cast<const int4*>(qw)[idx];
        int q[4] = {qv.x, qv.y, qv.z, qv.w};
        __nv_bfloat16 o[8];
#pragma unroll
        for (int e = 0; e < 4; e++) {
            o[2 * e]     = __float2bfloat16_rn((float)(((q[e] >> 4) & 15) - 8));  // high -> even col
            o[2 * e + 1] = __float2bfloat16_rn((float)((q[e] & 15) - 8));         // low  -> odd col
        }
        reinterpret_cast<uint4*>(g_wb)[idx] = *reinterpret_cast<uint4*>(o);
        return;
    }

    const int row = blockIdx.x;
    const float4* xr = reinterpret_cast<const float4*>(x + (size_t)row * IN_F);
    const int t = threadIdx.x;

    float4 v[4];
    float m = 0.f;
#pragma unroll
    for (int q = 0; q < 4; q++) {
        v[q] = xr[t + 256 * q];
        m = fmaxf(m, fmaxf(fmaxf(fabsf(v[q].x), fabsf(v[q].y)),
                           fmaxf(fabsf(v[q].z), fabsf(v[q].w))));
    }
#pragma unroll
    for (int o = 16; o > 0; o >>= 1) m = fmaxf(m, __shfl_xor_sync(0xffffffffu, m, o));

    __shared__ float wmax[8];
    __shared__ float s_scale;
    if ((t & 31) == 0) wmax[t >> 5] = m;
    __syncthreads();
    if (t == 0) {
        float mm = wmax[0];
#pragma unroll
        for (int i = 1; i < 8; i++) mm = fmaxf(mm, wmax[i]);
        float s = (mm == 0.f) ? 1.f : (mm / 127.f);
        s_scale = s;
        g_act_scale[row] = s;
    }
    __syncthreads();
    const float inv = 1.f / s_scale;

    uint2* orow = reinterpret_cast<uint2*>(g_act + (size_t)row * IN_F);
#pragma unroll
    for (int q = 0; q < 4; q++) {
        float q0 = fminf(fmaxf(rintf(v[q].x * inv), -128.f), 127.f);
        float q1 = fminf(fmaxf(rintf(v[q].y * inv), -128.f), 127.f);
        float q2 = fminf(fmaxf(rintf(v[q].z * inv), -128.f), 127.f);
        float q3 = fminf(fmaxf(rintf(v[q].w * inv), -128.f), 127.f);
        __nv_bfloat162 lo, hi;
        lo.x = __float2bfloat16_rn(q0); lo.y = __float2bfloat16_rn(q1);
        hi.x = __float2bfloat16_rn(q2); hi.y = __float2bfloat16_rn(q3);
        uint2 u;
        u.x = *reinterpret_cast<uint32_t*>(&lo);
        u.y = *reinterpret_cast<uint32_t*>(&hi);
        orow[t + 256 * q] = u;
    }
}

// ---------------- kernel 2: bf16 HMMA GEMM, 4 warps, 64x64 warp tiles ----------------
__global__ void __launch_bounds__(GT, 2) gemm_kernel(
    const float* __restrict__ wscale, const float* __restrict__ bias,
    float* __restrict__ out)
{
    extern __shared__ __align__(128) char smem[];
    const uint32_t sb = smem_u32(smem);

    const int tid  = threadIdx.x;
    const int wid  = tid >> 5;
    const int lane = tid & 31;
    const int n0 = blockIdx.x * BN;
    const int m0 = blockIdx.y * BM;

    const int wm = (wid & 1) * 64;    // 2 warps in m
    const int wn = (wid >> 1) * 64;   // 2 warps in n

    const char* Abase = reinterpret_cast<const char*>(g_act) + (size_t)m0 * IN_F * 2;
    const char* Bbase = reinterpret_cast<const char*>(g_wb)  + (size_t)n0 * IN_F * 2;

    // producer: 128 threads, A = 1024 16B-chunks -> 8/thread; B same
    uint32_t dA[8], gA[8];
#pragma unroll
    for (int q = 0; q < 8; q++) {
        uint32_t seg = (uint32_t)(q * GT + tid);
        uint32_t row = seg >> 3, kc = seg & 7;
        dA[q] = swz(row, kc);
        gA[q] = row * (IN_F * 2) + kc * 16;
    }

    // ldmatrix address bases (xor swizzle decomposed over disjoint bit fields)
    uint32_t baseA[4], eA[4], baseB[4], eB[4];
    {
        const uint32_t hA = (uint32_t)lane >> 4;
#pragma unroll
        for (int mt = 0; mt < 4; mt++) {
            uint32_t row = (uint32_t)(wm + mt * 16 + (lane & 15));
            uint32_t r7 = row & 7u;
            baseA[mt] = row * ROWB + ((hA ^ (r7 & 1u)) << 4);
            eA[mt] = r7 & 6u;
        }
        const uint32_t g = (uint32_t)lane >> 3;
        const uint32_t hB = g & 1u;
#pragma unroll
        for (int p = 0; p < 4; p++) {
            uint32_t row = (uint32_t)(wn + p * 16 + ((g >> 1) & 1u) * 8 + (lane & 7));
            uint32_t r7 = row & 7u;
            baseB[p] = (uint32_t)A_BYTES + row * ROWB + ((hB ^ (r7 & 1u)) << 4);
            eB[p] = r7 & 6u;
        }
    }

    float acc[4][8][4];
#pragma unroll
    for (int i = 0; i < 4; i++)
#pragma unroll
        for (int j = 0; j < 8; j++)
#pragma unroll
            for (int c = 0; c < 4; c++) acc[i][j][c] = 0.f;

#define LOAD_STAGE(J, S)                                                          \
    do {                                                                          \
        const uint32_t kof = (uint32_t)(J) * (BKE * 2);                           \
        const uint32_t st  = sb + (uint32_t)(S) * STAGE_BYTES;                    \
        _Pragma("unroll")                                                         \
        for (int q = 0; q < 8; q++) {                                             \
            cp16(st + dA[q], Abase + gA[q] + kof);                                \
            cp16(st + A_BYTES + dA[q], Bbase + gA[q] + kof);                      \
        }                                                                         \
        asm volatile("cp.async.commit_group;" ::: "memory");                      \
    } while (0)

    // prologue: scale/bias prefetch joins group 0; then stages 0,1
    cp4(sb + OFF_SCALE +        tid * 4, g_act_scale + m0 + tid);
    cp4(sb + OFF_SCALE +  512 + tid * 4, wscale + n0 + tid);
    cp4(sb + OFF_SCALE + 1024 + tid * 4, bias + n0 + tid);
    LOAD_STAGE(0, 0);
    LOAD_STAGE(1, 1);

    int stage = 0;
    for (int j = 0; j < NCHUNK; j++) {
        asm volatile("cp.async.wait_group 1;" ::: "memory");
        __syncthreads();

        int jn = j + STAGES - 1;
        int sn = stage + (STAGES - 1); if (sn >= STAGES) sn -= STAGES;
        if (jn < NCHUNK) LOAD_STAGE(jn, sn);
        else asm volatile("cp.async.commit_group;" ::: "memory");

        const uint32_t st = sb + (uint32_t)stage * STAGE_BYTES;
        if (++stage == STAGES) stage = 0;
#pragma unroll
        for (int ks = 0; ks < 4; ks++) {
            const uint32_t k2 = (uint32_t)(ks * 2) << 4;
            uint32_t a[4][4], b[4][4];
#pragma unroll
            for (int mt = 0; mt < 4; mt++)
                ldm_x4(a[mt], st + baseA[mt] + (k2 ^ (eA[mt] << 4)));
#pragma unroll
            for (int p = 0; p < 4; p++)
                ldm_x4(b[p], st + baseB[p] + (k2 ^ (eB[p] << 4)));
#pragma unroll
            for (int mt = 0; mt < 4; mt++) {
#pragma unroll
                for (int nt = 0; nt < 8; nt++) {
                    mma_bf16(acc[mt][nt], a[mt],
                             b[nt >> 1][(nt & 1) * 2], b[nt >> 1][(nt & 1) * 2 + 1]);
                }
            }
        }
    }

    // ---------------- epilogue (scales prefetched in group 0; no barrier, no global loads) ----------------
    const float* sAs = reinterpret_cast<const float*>(smem + OFF_SCALE);
    const float* sWs = reinterpret_cast<const float*>(smem + OFF_SCALE + 512);
    const float* sBi = reinterpret_cast<const float*>(smem + OFF_SCALE + 1024);

#pragma unroll
    for (int mt = 0; mt < 4; mt++) {
        const int r0 = wm + mt * 16 + (lane >> 2);
        const int r1 = r0 + 8;
        const float as0 = sAs[r0], as1 = sAs[r1];
#pragma unroll
        for (int nt = 0; nt < 8; nt++) {
            const int n = wn + nt * 8 + (lane & 3) * 2;
            const float w0 = sWs[n], w1 = sWs[n + 1];
            const float b0 = sBi[n], b1 = sBi[n + 1];
            float2 v0, v1;
            v0.x = acc[mt][nt][0] * (as0 * w0) + b0;
            v0.y = acc[mt][nt][1] * (as0 * w1) + b1;
            v1.x = acc[mt][nt][2] * (as1 * w0) + b0;
            v1.y = acc[mt][nt][3] * (as1 * w1) + b1;
            *reinterpret_cast<float2*>(&out[(size_t)(m0 + r0) * OUT_F + n0 + n]) = v0;
            *reinterpret_cast<float2*>(&out[(size_t)(m0 + r1) * OUT_F + n0 + n]) = v1;
        }
    }
}

// ---------------- launcher ----------------
extern "C" void kernel_launch(void* const* d_in, const int* in_sizes, int n_in,
                              void* d_out, int out_size)
{
    const float* x      = (const float*)d_in[0];
    const int*   qw     = (const int*)d_in[1];
    const float* wscale = (const float*)d_in[2];
    const float* bias   = (const float*)d_in[3];
    float* out          = (float*)d_out;

    prep_kernel<<<TOKENS + UNPACK_BLOCKS, 256>>>(x, qw);

    cudaFuncSetAttribute(gemm_kernel, cudaFuncAttributeMaxDynamicSharedMemorySize, SMEM_DYN);
    dim3 grid(OUT_F / BN, TOKENS / BM);
    gemm_kernel<<<grid, GT, SMEM_DYN>>>(wscale, bias, out);
}

// round 13
// speedup vs baseline: 1.0528x; 1.0528x over previous
#include <cuda_runtime.h>
#include <cuda_bf16.h>
#include <cstdint>

#define TOKENS 16384
#define IN_F   4096
#define OUT_F  4096

#define BM 128
#define BN 128
#define BKE 64                        // K elements per chunk
#define ROWB 128                      // bytes per smem row (64 bf16)
#define STAGES 3
#define NCHUNK (IN_F / BKE)           // 64
#define A_BYTES (BM * ROWB)           // 16 KB
#define STAGE_BYTES (2 * BM * ROWB)   // 32 KB
#define OFF_SCALE (STAGES * STAGE_BYTES)   // 98304: scale/bias staging
#define SMEM_DYN (OFF_SCALE + 1536)

#define UNPACK_BLOCKS ((OUT_F * (IN_F / 2) / 4) / 256)   // 8192

// ---------------- device scratch ----------------
__device__ __nv_bfloat16 g_act[(size_t)TOKENS * IN_F];   // 128 MB bf16 integer activations
__device__ float         g_act_scale[TOKENS];
__device__ __nv_bfloat16 g_wb[(size_t)OUT_F * IN_F];     // 32 MB bf16 integer weights (K-major)

// ---------------- helpers ----------------
__device__ __forceinline__ uint32_t smem_u32(const void* p) {
    uint32_t a;
    asm("{ .reg .u64 t; cvta.to.shared.u64 t, %1; cvt.u32.u64 %0, t; }" : "=r"(a) : "l"(p));
    return a;
}
// 16B-chunk xor swizzle within a 128B row: conflict-free for 8-row ldmatrix phases
__device__ __forceinline__ uint32_t swz(uint32_t row, uint32_t kc) {
    return row * ROWB + ((kc ^ (row & 7u)) << 4);
}
__device__ __forceinline__ void cp16(uint32_t d, const void* g) {
    asm volatile("cp.async.cg.shared.global [%0], [%1], 16;" :: "r"(d), "l"(g) : "memory");
}
__device__ __forceinline__ void cp4(uint32_t d, const void* g) {
    asm volatile("cp.async.ca.shared.global [%0], [%1], 4;" :: "r"(d), "l"(g) : "memory");
}
__device__ __forceinline__ void ldm_x4(uint32_t* r, uint32_t addr) {
    asm volatile("ldmatrix.sync.aligned.m8n8.x4.shared.b16 {%0,%1,%2,%3}, [%4];"
                 : "=r"(r[0]), "=r"(r[1]), "=r"(r[2]), "=r"(r[3]) : "r"(addr));
}
__device__ __forceinline__ void mma_bf16(float* c, const uint32_t* a, uint32_t b0, uint32_t b1) {
    asm volatile("mma.sync.aligned.m16n8k16.row.col.f32.bf16.bf16.f32 "
                 "{%0,%1,%2,%3}, {%4,%5,%6,%7}, {%8,%9}, {%0,%1,%2,%3};"
                 : "+f"(c[0]), "+f"(c[1]), "+f"(c[2]), "+f"(c[3])
                 : "r"(a[0]), "r"(a[1]), "r"(a[2]), "r"(a[3]), "r"(b0), "r"(b1));
}

// ---------------- kernel 1: fused prep (quant rows + weight unpack) ----------------
__global__ void __launch_bounds__(256) prep_kernel(const float* __restrict__ x,
                                                   const int* __restrict__ qw)
{
    if (blockIdx.x >= TOKENS) {
        size_t idx = (size_t)(blockIdx.x - TOKENS) * 256 + threadIdx.x;
        int4 qv = reinterpret_cast<const int4*>(qw)[idx];
        int q[4] = {qv.x, qv.y, qv.z, qv.w};
        __nv_bfloat16 o[8];
#pragma unroll
        for (int e = 0; e < 4; e++) {
            o[2 * e]     = __float2bfloat16_rn((float)(((q[e] >> 4) & 15) - 8));  // high -> even col
            o[2 * e + 1] = __float2bfloat16_rn((float)((q[e] & 15) - 8));         // low  -> odd col
        }
        reinterpret_cast<uint4*>(g_wb)[idx] = *reinterpret_cast<uint4*>(o);
        return;
    }

    const int row = blockIdx.x;
    const float4* xr = reinterpret_cast<const float4*>(x + (size_t)row * IN_F);
    const int t = threadIdx.x;

    float4 v[4];
    float m = 0.f;
#pragma unroll
    for (int q = 0; q < 4; q++) {
        v[q] = xr[t + 256 * q];
        m = fmaxf(m, fmaxf(fmaxf(fabsf(v[q].x), fabsf(v[q].y)),
                           fmaxf(fabsf(v[q].z), fabsf(v[q].w))));
    }
#pragma unroll
    for (int o = 16; o > 0; o >>= 1) m = fmaxf(m, __shfl_xor_sync(0xffffffffu, m, o));

    __shared__ float wmax[8];
    __shared__ float s_scale;
    if ((t & 31) == 0) wmax[t >> 5] = m;
    __syncthreads();
    if (t == 0) {
        float mm = wmax[0];
#pragma unroll
        for (int i = 1; i < 8; i++) mm = fmaxf(mm, wmax[i]);
        float s = (mm == 0.f) ? 1.f : (mm / 127.f);
        s_scale = s;
        g_act_scale[row] = s;
    }
    __syncthreads();
    const float inv = 1.f / s_scale;

    uint2* orow = reinterpret_cast<uint2*>(g_act + (size_t)row * IN_F);
#pragma unroll
    for (int q = 0; q < 4; q++) {
        float q0 = fminf(fmaxf(rintf(v[q].x * inv), -128.f), 127.f);
        float q1 = fminf(fmaxf(rintf(v[q].y * inv), -128.f), 127.f);
        float q2 = fminf(fmaxf(rintf(v[q].z * inv), -128.f), 127.f);
        float q3 = fminf(fmaxf(rintf(v[q].w * inv), -128.f), 127.f);
        __nv_bfloat162 lo, hi;
        lo.x = __float2bfloat16_rn(q0); lo.y = __float2bfloat16_rn(q1);
        hi.x = __float2bfloat16_rn(q2); hi.y = __float2bfloat16_rn(q3);
        uint2 u;
        u.x = *reinterpret_cast<uint32_t*>(&lo);
        u.y = *reinterpret_cast<uint32_t*>(&hi);
        orow[t + 256 * q] = u;
    }
}

// ---------------- kernel 2: bf16 HMMA GEMM + fused dequant ----------------
__global__ void __launch_bounds__(256, 2) gemm_kernel(
    const float* __restrict__ wscale, const float* __restrict__ bias,
    float* __restrict__ out)
{
    extern __shared__ __align__(128) char smem[];
    const uint32_t sb = smem_u32(smem);

    const int tid  = threadIdx.x;
    const int wid  = tid >> 5;
    const int lane = tid & 31;
    const int n0 = blockIdx.x * BN;
    const int m0 = blockIdx.y * BM;

    const int wm = (wid & 1) * 64;    // 2 warps in m
    const int wn = (wid >> 1) * 32;   // 4 warps in n

    const char* Abase = reinterpret_cast<const char*>(g_act) + (size_t)m0 * IN_F * 2;
    const char* Bbase = reinterpret_cast<const char*>(g_wb)  + (size_t)n0 * IN_F * 2;

    // producer: each thread copies 4 A-chunks and 4 B-chunks (16B each) per stage
    uint32_t dA[4], gA[4];
#pragma unroll
    for (int q = 0; q < 4; q++) {
        uint32_t seg = (uint32_t)(q * 256 + tid);
        uint32_t row = seg >> 3, kc = seg & 7;
        dA[q] = swz(row, kc);
        gA[q] = row * (IN_F * 2) + kc * 16;
    }

    // ldmatrix address bases (xor swizzle decomposed over disjoint bit fields)
    uint32_t baseA[4], eA[4], baseB[2], eB[2];
    {
        const uint32_t hA = (uint32_t)lane >> 4;
#pragma unroll
        for (int mt = 0; mt < 4; mt++) {
            uint32_t row = (uint32_t)(wm + mt * 16 + (lane & 15));
            uint32_t r7 = row & 7u;
            baseA[mt] = row * ROWB + ((hA ^ (r7 & 1u)) << 4);
            eA[mt] = r7 & 6u;
        }
        const uint32_t g = (uint32_t)lane >> 3;
        const uint32_t hB = g & 1u;
#pragma unroll
        for (int p = 0; p < 2; p++) {
            uint32_t row = (uint32_t)(wn + p * 16 + ((g >> 1) & 1u) * 8 + (lane & 7));
            uint32_t r7 = row & 7u;
            baseB[p] = (uint32_t)A_BYTES + row * ROWB + ((hB ^ (r7 & 1u)) << 4);
            eB[p] = r7 & 6u;
        }
    }

    float acc[4][4][4];
#pragma unroll
    for (int i = 0; i < 4; i++)
#pragma unroll
        for (int j = 0; j < 4; j++)
#pragma unroll
            for (int c = 0; c < 4; c++) acc[i][j][c] = 0.f;

#define LOAD_STAGE(J, S)                                                          \
    do {                                                                          \
        const uint32_t kof = (uint32_t)(J) * (BKE * 2);                           \
        const uint32_t st  = sb + (uint32_t)(S) * STAGE_BYTES;                    \
        cp16(st + dA[0], Abase + gA[0] + kof);                                    \
        cp16(st + dA[1], Abase + gA[1] + kof);                                    \
        cp16(st + dA[2], Abase + gA[2] + kof);                                    \
        cp16(st + dA[3], Abase + gA[3] + kof);                                    \
        cp16(st + A_BYTES + dA[0], Bbase + gA[0] + kof);                          \
        cp16(st + A_BYTES + dA[1], Bbase + gA[1] + kof);                          \
        cp16(st + A_BYTES + dA[2], Bbase + gA[2] + kof);                          \
        cp16(st + A_BYTES + dA[3], Bbase + gA[3] + kof);                          \
        asm volatile("cp.async.commit_group;" ::: "memory");                      \
    } while (0)

    // prologue: scale/bias prefetch joins group 0; then stages 0,1
    if (tid < 128) {
        cp4(sb + OFF_SCALE +        tid * 4, g_act_scale + m0 + tid);
        cp4(sb + OFF_SCALE +  512 + tid * 4, wscale + n0 + tid);
        cp4(sb + OFF_SCALE + 1024 + tid * 4, bias + n0 + tid);
    }
    LOAD_STAGE(0, 0);
    LOAD_STAGE(1, 1);

    // Loop order: wait(j) -> BARRIER -> compute(j) -> issue(j+2).
    // Barrier sits between wait and compute (cp.async completion is per-thread;
    // the barrier is what makes other threads' fills visible — R12 lesson).
    // issue(j+2) overwrites slot (j-1)%3; every thread finished compute(j-1)
    // before passing THIS iteration's barrier, so no WAR hazard.
    // At wait(j), pending groups = {j, j+1} -> wait_group 1 = stage-j complete.
    int stage = 0;
    for (int j = 0; j < NCHUNK; j++) {
        asm volatile("cp.async.wait_group 1;" ::: "memory");
        __syncthreads();

        const uint32_t st = sb + (uint32_t)stage * STAGE_BYTES;
#pragma unroll
        for (int ks = 0; ks < 4; ks++) {
            const uint32_t k2 = (uint32_t)(ks * 2) << 4;
            uint32_t a[4][4], b[2][4];
#pragma unroll
            for (int mt = 0; mt < 4; mt++)
                ldm_x4(a[mt], st + baseA[mt] + (k2 ^ (eA[mt] << 4)));
#pragma unroll
            for (int p = 0; p < 2; p++)
                ldm_x4(b[p], st + baseB[p] + (k2 ^ (eB[p] << 4)));
#pragma unroll
            for (int mt = 0; mt < 4; mt++) {
#pragma unroll
                for (int nt = 0; nt < 4; nt++) {
                    mma_bf16(acc[mt][nt], a[mt],
                             b[nt >> 1][(nt & 1) * 2], b[nt >> 1][(nt & 1) * 2 + 1]);
                }
            }
        }

        int jn = j + STAGES - 1;
        int sn = stage + (STAGES - 1); if (sn >= STAGES) sn -= STAGES;
        if (jn < NCHUNK) LOAD_STAGE(jn, sn);
        else asm volatile("cp.async.commit_group;" ::: "memory");

        if (++stage == STAGES) stage = 0;
    }

    // ---------------- epilogue (scales prefetched in group 0; no barrier, no global loads) ----------------
    const float* sAs = reinterpret_cast<const float*>(smem + OFF_SCALE);
    const float* sWs = reinterpret_cast<const float*>(smem + OFF_SCALE + 512);
    const float* sBi = reinterpret_cast<const float*>(smem + OFF_SCALE + 1024);

#pragma unroll
    for (int mt = 0; mt < 4; mt++) {
        const int r0 = wm + mt * 16 + (lane >> 2);
        const int r1 = r0 + 8;
        const float as0 = sAs[r0], as1 = sAs[r1];
#pragma unroll
        for (int nt = 0; nt < 4; nt++) {
            const int n = wn + nt * 8 + (lane & 3) * 2;
            const float w0 = sWs[n], w1 = sWs[n + 1];
            const float b0 = sBi[n], b1 = sBi[n + 1];
            float2 v0, v1;
            v0.x = acc[mt][nt][0] * (as0 * w0) + b0;
            v0.y = acc[mt][nt][1] * (as0 * w1) + b1;
            v1.x = acc[mt][nt][2] * (as1 * w0) + b0;
            v1.y = acc[mt][nt][3] * (as1 * w1) + b1;
            *reinterpret_cast<float2*>(&out[(size_t)(m0 + r0) * OUT_F + n0 + n]) = v0;
            *reinterpret_cast<float2*>(&out[(size_t)(m0 + r1) * OUT_F + n0 + n]) = v1;
        }
    }
}

// ---------------- launcher ----------------
extern "C" void kernel_launch(void* const* d_in, const int* in_sizes, int n_in,
                              void* d_out, int out_size)
{
    const float* x      = (const float*)d_in[0];
    const int*   qw     = (const int*)d_in[1];
    const float* wscale = (const float*)d_in[2];
    const float* bias   = (const float*)d_in[3];
    float* out          = (float*)d_out;

    prep_kernel<<<TOKENS + UNPACK_BLOCKS, 256>>>(x, qw);

    cudaFuncSetAttribute(gemm_kernel, cudaFuncAttributeMaxDynamicSharedMemorySize, SMEM_DYN);
    dim3 grid(OUT_F / BN, TOKENS / BM);
    gemm_kernel<<<grid, 256, SMEM_DYN>>>(wscale, bias, out);
}